// round 7
// baseline (speedup 1.0000x reference)
#include <cuda_runtime.h>
#include <cuda_bf16.h>
#include <cstdint>

// Problem constants
#define NROWS   200000
#define FEAT    256
#define NCLASS  1000
#define NIMG    64
#define KPI     100
#define NSEG    4              // sub-counters per class (cuts same-address atomic serialization)
#define SEGCAP  128            // slots per segment (expected ~50/segment, max ~80)
#define SLOTS   (NSEG*SEGCAP)  // 512 rows-per-class capacity
#define CPAD    32             // 1 counter per 128B L2 line
#define COOC_RPB 4             // cooc output rows per CTA

// Output layout (float32): [protos 256000][init 1000][cooc 1000000]
#define OUT_PROTO 0
#define OUT_INIT  (NCLASS*FEAT)
#define OUT_COOC  (NCLASS*FEAT + NCLASS)

// ---------------- device scratch (no allocation allowed) ----------------
// Invariant: all (class, seg) counters are zero at kernel_launch entry.
// Zero-initialized statics cover call #1; k_class_accum re-zeros AFTER the
// block barrier that follows all reads.
// Each (class, seg) counter lives on its own 128B line: R5/R6 showed the
// scatter time is occupancy-invariant ~8us == per-address L2 atomic
// serialization (~200 ops/line). 4 sub-counters -> ~50 ops/line.
__device__ int g_cursor_pad[NCLASS * NSEG * CPAD];
__device__ int g_rowidx[NCLASS * SLOTS];

// ---------------- K1: scatter rows into padded per-class lists ----------
// 2 rows per thread. Row r of class c goes to segment (r & 3), slot from
// that segment's private line-padded counter.
__global__ void __launch_bounds__(256)
k_scatter(const int* __restrict__ labels) {
    int i = blockIdx.x * blockDim.x + threadIdx.x;
    if (i < NROWS / 2) {
        int2 l = __ldg(reinterpret_cast<const int2*>(labels) + i);
        int r0 = 2 * i, r1 = 2 * i + 1;
        int s0 = r0 & (NSEG - 1);
        int s1 = r1 & (NSEG - 1);
        int p0 = atomicAdd(&g_cursor_pad[(l.x * NSEG + s0) * CPAD], 1);
        int p1 = atomicAdd(&g_cursor_pad[(l.y * NSEG + s1) * CPAD], 1);
        if (p0 < SEGCAP) g_rowidx[l.x * SLOTS + s0 * SEGCAP + p0] = r0;
        if (p1 < SEGCAP) g_rowidx[l.y * SLOTS + s1 * SEGCAP + p1] = r1;
    }
}

// ---------------- K2 helper: warp-strided row accumulation ---------------
__device__ __forceinline__ void accum_rows(const float* __restrict__ features,
                                           const int* __restrict__ rows,
                                           int count, int warp, int lane,
                                           float acc[8])
{
    int r = warp;
    while (r + 24 < count) {
        int row0 = __ldg(&rows[r]);
        int row1 = __ldg(&rows[r + 8]);
        int row2 = __ldg(&rows[r + 16]);
        int row3 = __ldg(&rows[r + 24]);
        const float4* rp0 = reinterpret_cast<const float4*>(features + (size_t)row0 * FEAT);
        const float4* rp1 = reinterpret_cast<const float4*>(features + (size_t)row1 * FEAT);
        const float4* rp2 = reinterpret_cast<const float4*>(features + (size_t)row2 * FEAT);
        const float4* rp3 = reinterpret_cast<const float4*>(features + (size_t)row3 * FEAT);
        float4 a0 = __ldg(&rp0[lane * 2 + 0]);
        float4 b0 = __ldg(&rp0[lane * 2 + 1]);
        float4 a1 = __ldg(&rp1[lane * 2 + 0]);
        float4 b1 = __ldg(&rp1[lane * 2 + 1]);
        float4 a2 = __ldg(&rp2[lane * 2 + 0]);
        float4 b2 = __ldg(&rp2[lane * 2 + 1]);
        float4 a3 = __ldg(&rp3[lane * 2 + 0]);
        float4 b3 = __ldg(&rp3[lane * 2 + 1]);

        float s0 = a0.x*a0.x + a0.y*a0.y + a0.z*a0.z + a0.w*a0.w
                 + b0.x*b0.x + b0.y*b0.y + b0.z*b0.z + b0.w*b0.w;
        float s1 = a1.x*a1.x + a1.y*a1.y + a1.z*a1.z + a1.w*a1.w
                 + b1.x*b1.x + b1.y*b1.y + b1.z*b1.z + b1.w*b1.w;
        float s2 = a2.x*a2.x + a2.y*a2.y + a2.z*a2.z + a2.w*a2.w
                 + b2.x*b2.x + b2.y*b2.y + b2.z*b2.z + b2.w*b2.w;
        float s3 = a3.x*a3.x + a3.y*a3.y + a3.z*a3.z + a3.w*a3.w
                 + b3.x*b3.x + b3.y*b3.y + b3.z*b3.z + b3.w*b3.w;
        #pragma unroll
        for (int off = 16; off > 0; off >>= 1) {
            s0 += __shfl_xor_sync(0xffffffffu, s0, off);
            s1 += __shfl_xor_sync(0xffffffffu, s1, off);
            s2 += __shfl_xor_sync(0xffffffffu, s2, off);
            s3 += __shfl_xor_sync(0xffffffffu, s3, off);
        }
        float i0 = 1.0f / fmaxf(sqrtf(s0), 1e-12f);
        float i1 = 1.0f / fmaxf(sqrtf(s1), 1e-12f);
        float i2 = 1.0f / fmaxf(sqrtf(s2), 1e-12f);
        float i3 = 1.0f / fmaxf(sqrtf(s3), 1e-12f);
        acc[0] += a0.x*i0 + a1.x*i1 + a2.x*i2 + a3.x*i3;
        acc[1] += a0.y*i0 + a1.y*i1 + a2.y*i2 + a3.y*i3;
        acc[2] += a0.z*i0 + a1.z*i1 + a2.z*i2 + a3.z*i3;
        acc[3] += a0.w*i0 + a1.w*i1 + a2.w*i2 + a3.w*i3;
        acc[4] += b0.x*i0 + b1.x*i1 + b2.x*i2 + b3.x*i3;
        acc[5] += b0.y*i0 + b1.y*i1 + b2.y*i2 + b3.y*i3;
        acc[6] += b0.z*i0 + b1.z*i1 + b2.z*i2 + b3.z*i3;
        acc[7] += b0.w*i0 + b1.w*i1 + b2.w*i2 + b3.w*i3;
        r += 32;
    }
    while (r < count) {
        int row = __ldg(&rows[r]);
        const float4* rp = reinterpret_cast<const float4*>(features + (size_t)row * FEAT);
        float4 a = __ldg(&rp[lane * 2 + 0]);
        float4 b = __ldg(&rp[lane * 2 + 1]);
        float s = a.x*a.x + a.y*a.y + a.z*a.z + a.w*a.w
                + b.x*b.x + b.y*b.y + b.z*b.z + b.w*b.w;
        #pragma unroll
        for (int off = 16; off > 0; off >>= 1)
            s += __shfl_xor_sync(0xffffffffu, s, off);
        float inv = 1.0f / fmaxf(sqrtf(s), 1e-12f);
        acc[0] += a.x*inv; acc[1] += a.y*inv; acc[2] += a.z*inv; acc[3] += a.w*inv;
        acc[4] += b.x*inv; acc[5] += b.y*inv; acc[6] += b.z*inv; acc[7] += b.w*inv;
        r += 8;
    }
}

// ---------------- K2: per-class normalize+sum, EMA, write protos ---------
__global__ void __launch_bounds__(256, 4)
k_class_accum(const float* __restrict__ features,
              const float* __restrict__ prototypes,
              const int*   __restrict__ init_mask,
              const int*   __restrict__ step_ptr,
              float*       __restrict__ out)
{
    int c    = blockIdx.x;
    int tid  = threadIdx.x;
    int warp = tid >> 5;
    int lane = tid & 31;

    int cnt[NSEG];
    int count = 0;
    #pragma unroll
    for (int s = 0; s < NSEG; ++s) {
        cnt[s] = min(g_cursor_pad[(c * NSEG + s) * CPAD], SEGCAP);
        count += cnt[s];
    }
    const int* __restrict__ rows = &g_rowidx[c * SLOTS];

    float acc[8];
    #pragma unroll
    for (int j = 0; j < 8; ++j) acc[j] = 0.f;

    #pragma unroll
    for (int s = 0; s < NSEG; ++s)
        accum_rows(features, rows + s * SEGCAP, cnt[s], warp, lane, acc);

    // combine 8 warps' partials: warp w's lane l owns cols [8l, 8l+8)
    __shared__ float sacc[8][FEAT];
    #pragma unroll
    for (int j = 0; j < 8; ++j) sacc[warp][lane * 8 + j] = acc[j];
    __syncthreads();

    // SAFE cleanup point: barrier above guarantees every thread consumed
    // the counts, and no other CTA touches this class's counters.
    if (tid < NSEG) g_cursor_pad[(c * NSEG + tid) * CPAD] = 0;

    int col = tid;
    float sum = 0.f;
    #pragma unroll
    for (int w = 0; w < 8; ++w) sum += sacc[w][col];

    float mean  = sum / fmaxf((float)count, 1.0f);
    float proto = __ldg(&prototypes[(size_t)c * FEAT + col]);

    int   step     = step_ptr ? __ldg(step_ptr) : 5000;
    float progress = fminf(1.0f, (float)step / 2000.0f);   // WARMUP_STEPS*10
    float m        = 0.99f + (0.999f - 0.99f) * progress;

    bool present = (count > 0);
    bool inited  = (__ldg(&init_mask[c]) > 0);

    float np;
    if (present && inited) np = m * proto + (1.0f - m) * mean;
    else if (present)      np = mean;
    else                   np = proto;

    out[OUT_PROTO + (size_t)c * FEAT + col] = np;
    if (tid == 0)
        out[OUT_INIT + c] = (inited || present) ? 1.0f : 0.0f;
}

// ---------------- K3: co-occurrence ---------------------------------------
// 250 CTAs, each producing COOC_RPB=4 output rows; the 8KB presence-
// bitmask table is rebuilt once per CTA.
__global__ void __launch_bounds__(256)
k_cooc(const int* __restrict__ lpi,
       const float* __restrict__ cooc_in,
       float* __restrict__ out)
{
    __shared__ unsigned long long scol[NCLASS];
    int t = threadIdx.x;

    for (int k = t; k < NCLASS; k += 256) scol[k] = 0ULL;
    __syncthreads();

    for (int k = t; k < NIMG * KPI; k += 256) {
        int img = k / KPI;
        atomicOr(&scol[__ldg(&lpi[k])], 1ULL << img);
    }
    __syncthreads();

    int i0 = blockIdx.x * COOC_RPB;
    if (t < NCLASS / 4) {
        int j0 = t * 4;
        unsigned long long c0 = scol[j0 + 0];
        unsigned long long c1 = scol[j0 + 1];
        unsigned long long c2 = scol[j0 + 2];
        unsigned long long c3 = scol[j0 + 3];
        #pragma unroll
        for (int rr = 0; rr < COOC_RPB; ++rr) {
            int i = i0 + rr;
            unsigned long long bi = scol[i];
            const float4* in4 = reinterpret_cast<const float4*>(cooc_in + (size_t)i * NCLASS) + t;
            float4 v = __ldg(in4);
            v.x += (i == j0 + 0) ? 0.f : (float)__popcll(bi & c0);
            v.y += (i == j0 + 1) ? 0.f : (float)__popcll(bi & c1);
            v.z += (i == j0 + 2) ? 0.f : (float)__popcll(bi & c2);
            v.w += (i == j0 + 3) ? 0.f : (float)__popcll(bi & c3);
            reinterpret_cast<float4*>(out + OUT_COOC + (size_t)i * NCLASS)[t] = v;
        }
    }
}

// ---------------- launch ------------------------------------------------
extern "C" void kernel_launch(void* const* d_in, const int* in_sizes, int n_in,
                              void* d_out, int out_size)
{
    const float* features   = (const float*)d_in[0];
    const int*   labels     = (const int*)  d_in[1];
    const int*   lpi        = (const int*)  d_in[2];
    const float* prototypes = (const float*)d_in[3];
    const int*   init_mask  = (const int*)  d_in[4];
    const float* cooc_in    = (const float*)d_in[5];
    const int*   step_ptr   = (n_in >= 7) ? (const int*)d_in[6] : nullptr;
    float*       out        = (float*)d_out;

    k_scatter<<<(NROWS / 2 + 255) / 256, 256>>>(labels);
    k_class_accum<<<NCLASS, 256>>>(features, prototypes, init_mask, step_ptr, out);
    k_cooc<<<NCLASS / COOC_RPB, 256>>>(lpi, cooc_in, out);
}

// round 8
// speedup vs baseline: 1.0926x; 1.0926x over previous
#include <cuda_runtime.h>
#include <cuda_bf16.h>
#include <cstdint>

// Problem constants
#define NROWS   200000
#define FEAT    256
#define NCLASS  1000
#define NIMG    64
#define KPI     100
#define SLOTS   512            // padded rows-per-class capacity (max actual ~270)
#define CPAD    32             // cursor padding: 1 counter per 128B L2 line
#define COOC_RPB 4             // cooc output rows per CTA
#define FUSED_GRID (NCLASS / COOC_RPB)   // 250 CTAs

// Output layout (float32): [protos 256000][init 1000][cooc 1000000]
#define OUT_PROTO 0
#define OUT_INIT  (NCLASS*FEAT)
#define OUT_COOC  (NCLASS*FEAT + NCLASS)

// ---------------- device scratch (no allocation allowed) ----------------
// Invariant: g_cursor_pad counters are all-zero at kernel_launch entry.
// Zero-initialized statics cover call #1; k_class_accum re-zeros each
// element AFTER the block barrier that follows all reads of it.
// One counter per 128B line (R4->R5 cut scatter 20->8us; further counter
// splitting (R7) did nothing — scatter is at its serialization floor, so
// we hide it behind cooc's streaming instead).
__device__ int g_cursor_pad[NCLASS * CPAD];
__device__ int g_rowidx[NCLASS * SLOTS];

// ---------------- K1 (fused): cooc update + row scatter ------------------
// cooc and scatter are mutually independent (only k_class_accum consumes
// the scatter results), so one kernel does both: scatter's L2-atomic
// serialization latency overlaps with cooc's 16MB streaming traffic.
__global__ void __launch_bounds__(256)
k_cooc_scatter(const int* __restrict__ labels,
               const int* __restrict__ lpi,
               const float* __restrict__ cooc_in,
               float* __restrict__ out)
{
    __shared__ unsigned long long scol[NCLASS];
    int t   = threadIdx.x;
    int bid = blockIdx.x;

    // --- build presence bitmask table (8KB smem, once per CTA) ---
    for (int k = t; k < NCLASS; k += 256) scol[k] = 0ULL;
    __syncthreads();
    for (int k = t; k < NIMG * KPI; k += 256) {
        int img = k / KPI;
        atomicOr(&scol[__ldg(&lpi[k])], 1ULL << img);
    }

    // --- scatter slice: grid-stride over int2 label pairs ---
    // (issued between the two cooc phases so the atomic chains retire
    // while other warps stream cooc rows)
    for (int i = bid * 256 + t; i < NROWS / 2; i += FUSED_GRID * 256) {
        int2 l = __ldg(reinterpret_cast<const int2*>(labels) + i);
        int p0 = atomicAdd(&g_cursor_pad[l.x * CPAD], 1);
        int p1 = atomicAdd(&g_cursor_pad[l.y * CPAD], 1);
        int r = 2 * i;
        if (p0 < SLOTS) g_rowidx[l.x * SLOTS + p0] = r + 0;
        if (p1 < SLOTS) g_rowidx[l.y * SLOTS + p1] = r + 1;
    }

    __syncthreads();   // scol table complete before reads

    // --- cooc rows: COOC_RPB rows per CTA ---
    int i0 = bid * COOC_RPB;
    if (t < NCLASS / 4) {
        int j0 = t * 4;
        unsigned long long c0 = scol[j0 + 0];
        unsigned long long c1 = scol[j0 + 1];
        unsigned long long c2 = scol[j0 + 2];
        unsigned long long c3 = scol[j0 + 3];
        #pragma unroll
        for (int rr = 0; rr < COOC_RPB; ++rr) {
            int i = i0 + rr;
            unsigned long long bi = scol[i];
            const float4* in4 = reinterpret_cast<const float4*>(cooc_in + (size_t)i * NCLASS) + t;
            float4 v = __ldg(in4);
            v.x += (i == j0 + 0) ? 0.f : (float)__popcll(bi & c0);
            v.y += (i == j0 + 1) ? 0.f : (float)__popcll(bi & c1);
            v.z += (i == j0 + 2) ? 0.f : (float)__popcll(bi & c2);
            v.w += (i == j0 + 3) ? 0.f : (float)__popcll(bi & c3);
            reinterpret_cast<float4*>(out + OUT_COOC + (size_t)i * NCLASS)[t] = v;
        }
    }
}

// ---------------- K2: per-class normalize+sum, EMA, write protos ---------
// 1000 CTAs (one per class), 8 warps. Each warp owns whole rows; lane l
// loads cols [8l,8l+8) as two float4. Four rows in flight per iteration.
// Row norms via warp shfl reduce; no block barriers inside the loop.
// (R7 showed splitting the list into short segments kills the pipelined
// loop — keep one contiguous list per class.)
__global__ void __launch_bounds__(256, 4)
k_class_accum(const float* __restrict__ features,
              const float* __restrict__ prototypes,
              const int*   __restrict__ init_mask,
              const int*   __restrict__ step_ptr,
              float*       __restrict__ out)
{
    int c    = blockIdx.x;
    int tid  = threadIdx.x;
    int warp = tid >> 5;
    int lane = tid & 31;

    int count = min(g_cursor_pad[c * CPAD], SLOTS);
    const int* __restrict__ rows = &g_rowidx[c * SLOTS];

    float acc[8];
    #pragma unroll
    for (int j = 0; j < 8; ++j) acc[j] = 0.f;

    int r = warp;
    while (r + 24 < count) {
        int row0 = __ldg(&rows[r]);
        int row1 = __ldg(&rows[r + 8]);
        int row2 = __ldg(&rows[r + 16]);
        int row3 = __ldg(&rows[r + 24]);
        const float4* rp0 = reinterpret_cast<const float4*>(features + (size_t)row0 * FEAT);
        const float4* rp1 = reinterpret_cast<const float4*>(features + (size_t)row1 * FEAT);
        const float4* rp2 = reinterpret_cast<const float4*>(features + (size_t)row2 * FEAT);
        const float4* rp3 = reinterpret_cast<const float4*>(features + (size_t)row3 * FEAT);
        float4 a0 = __ldg(&rp0[lane * 2 + 0]);
        float4 b0 = __ldg(&rp0[lane * 2 + 1]);
        float4 a1 = __ldg(&rp1[lane * 2 + 0]);
        float4 b1 = __ldg(&rp1[lane * 2 + 1]);
        float4 a2 = __ldg(&rp2[lane * 2 + 0]);
        float4 b2 = __ldg(&rp2[lane * 2 + 1]);
        float4 a3 = __ldg(&rp3[lane * 2 + 0]);
        float4 b3 = __ldg(&rp3[lane * 2 + 1]);

        float s0 = a0.x*a0.x + a0.y*a0.y + a0.z*a0.z + a0.w*a0.w
                 + b0.x*b0.x + b0.y*b0.y + b0.z*b0.z + b0.w*b0.w;
        float s1 = a1.x*a1.x + a1.y*a1.y + a1.z*a1.z + a1.w*a1.w
                 + b1.x*b1.x + b1.y*b1.y + b1.z*b1.z + b1.w*b1.w;
        float s2 = a2.x*a2.x + a2.y*a2.y + a2.z*a2.z + a2.w*a2.w
                 + b2.x*b2.x + b2.y*b2.y + b2.z*b2.z + b2.w*b2.w;
        float s3 = a3.x*a3.x + a3.y*a3.y + a3.z*a3.z + a3.w*a3.w
                 + b3.x*b3.x + b3.y*b3.y + b3.z*b3.z + b3.w*b3.w;
        #pragma unroll
        for (int off = 16; off > 0; off >>= 1) {
            s0 += __shfl_xor_sync(0xffffffffu, s0, off);
            s1 += __shfl_xor_sync(0xffffffffu, s1, off);
            s2 += __shfl_xor_sync(0xffffffffu, s2, off);
            s3 += __shfl_xor_sync(0xffffffffu, s3, off);
        }
        float i0 = 1.0f / fmaxf(sqrtf(s0), 1e-12f);
        float i1 = 1.0f / fmaxf(sqrtf(s1), 1e-12f);
        float i2 = 1.0f / fmaxf(sqrtf(s2), 1e-12f);
        float i3 = 1.0f / fmaxf(sqrtf(s3), 1e-12f);
        acc[0] += a0.x*i0 + a1.x*i1 + a2.x*i2 + a3.x*i3;
        acc[1] += a0.y*i0 + a1.y*i1 + a2.y*i2 + a3.y*i3;
        acc[2] += a0.z*i0 + a1.z*i1 + a2.z*i2 + a3.z*i3;
        acc[3] += a0.w*i0 + a1.w*i1 + a2.w*i2 + a3.w*i3;
        acc[4] += b0.x*i0 + b1.x*i1 + b2.x*i2 + b3.x*i3;
        acc[5] += b0.y*i0 + b1.y*i1 + b2.y*i2 + b3.y*i3;
        acc[6] += b0.z*i0 + b1.z*i1 + b2.z*i2 + b3.z*i3;
        acc[7] += b0.w*i0 + b1.w*i1 + b2.w*i2 + b3.w*i3;
        r += 32;
    }
    while (r < count) {
        int row = __ldg(&rows[r]);
        const float4* rp = reinterpret_cast<const float4*>(features + (size_t)row * FEAT);
        float4 a = __ldg(&rp[lane * 2 + 0]);
        float4 b = __ldg(&rp[lane * 2 + 1]);
        float s = a.x*a.x + a.y*a.y + a.z*a.z + a.w*a.w
                + b.x*b.x + b.y*b.y + b.z*b.z + b.w*b.w;
        #pragma unroll
        for (int off = 16; off > 0; off >>= 1)
            s += __shfl_xor_sync(0xffffffffu, s, off);
        float inv = 1.0f / fmaxf(sqrtf(s), 1e-12f);
        acc[0] += a.x*inv; acc[1] += a.y*inv; acc[2] += a.z*inv; acc[3] += a.w*inv;
        acc[4] += b.x*inv; acc[5] += b.y*inv; acc[6] += b.z*inv; acc[7] += b.w*inv;
        r += 8;
    }

    // combine 8 warps' partials: warp w's lane l owns cols [8l, 8l+8)
    __shared__ float sacc[8][FEAT];
    #pragma unroll
    for (int j = 0; j < 8; ++j) sacc[warp][lane * 8 + j] = acc[j];
    __syncthreads();

    // SAFE cleanup point: barrier above guarantees every thread consumed
    // `count`; no other CTA touches g_cursor_pad[c*CPAD].
    if (tid == 0) g_cursor_pad[c * CPAD] = 0;

    int col = tid;
    float sum = 0.f;
    #pragma unroll
    for (int w = 0; w < 8; ++w) sum += sacc[w][col];

    float mean  = sum / fmaxf((float)count, 1.0f);
    float proto = __ldg(&prototypes[(size_t)c * FEAT + col]);

    int   step     = step_ptr ? __ldg(step_ptr) : 5000;
    float progress = fminf(1.0f, (float)step / 2000.0f);   // WARMUP_STEPS*10
    float m        = 0.99f + (0.999f - 0.99f) * progress;

    bool present = (count > 0);
    bool inited  = (__ldg(&init_mask[c]) > 0);

    float np;
    if (present && inited) np = m * proto + (1.0f - m) * mean;
    else if (present)      np = mean;
    else                   np = proto;

    out[OUT_PROTO + (size_t)c * FEAT + col] = np;
    if (tid == 0)
        out[OUT_INIT + c] = (inited || present) ? 1.0f : 0.0f;
}

// ---------------- launch ------------------------------------------------
extern "C" void kernel_launch(void* const* d_in, const int* in_sizes, int n_in,
                              void* d_out, int out_size)
{
    const float* features   = (const float*)d_in[0];
    const int*   labels     = (const int*)  d_in[1];
    const int*   lpi        = (const int*)  d_in[2];
    const float* prototypes = (const float*)d_in[3];
    const int*   init_mask  = (const int*)  d_in[4];
    const float* cooc_in    = (const float*)d_in[5];
    const int*   step_ptr   = (n_in >= 7) ? (const int*)d_in[6] : nullptr;
    float*       out        = (float*)d_out;

    k_cooc_scatter<<<FUSED_GRID, 256>>>(labels, lpi, cooc_in, out);
    k_class_accum<<<NCLASS, 256>>>(features, prototypes, init_mask, step_ptr, out);
}

// round 9
// speedup vs baseline: 1.4338x; 1.3122x over previous
#include <cuda_runtime.h>
#include <cuda_bf16.h>
#include <cstdint>

// Problem constants
#define NROWS   200000
#define FEAT    256
#define NCLASS  1000
#define NIMG    64
#define KPI     100
#define SLOTS   512            // padded rows-per-class capacity (max actual ~270)
#define CPAD    32             // cursor padding: 1 counter per 128B L2 line
#define COOC_RPB 4             // cooc output rows per CTA
#define COOC_CTAS   (NCLASS / COOC_RPB)          // 250
#define SCAT_CTAS   ((NROWS/2 + 255) / 256)      // 391
#define K1_GRID     (COOC_CTAS + SCAT_CTAS)      // 641 -> single wave

// Output layout (float32): [protos 256000][init 1000][cooc 1000000]
#define OUT_PROTO 0
#define OUT_INIT  (NCLASS*FEAT)
#define OUT_COOC  (NCLASS*FEAT + NCLASS)

// ---------------- device scratch (no allocation allowed) ----------------
// Invariant: g_cursor_pad counters are all-zero at kernel_launch entry.
// Zero-initialized statics cover call #1; k_class_accum re-zeros each
// element AFTER the block barrier that follows all reads of it.
__device__ int g_cursor_pad[NCLASS * CPAD];
__device__ int g_rowidx[NCLASS * SLOTS];

// ---------------- K1: grid-specialized cooc | scatter ---------------------
// R8 lesson: fusing independent phases into the SAME threads serializes
// (sum, not max). Instead, different CTAs take different roles in one
// launch: CTAs [0,250) stream the cooc update, CTAs [250,641) do the row
// scatter. Both are independent; they genuinely overlap, so the scatter's
// L2-atomic serialization hides under cooc's 16MB of streaming traffic.
__global__ void __launch_bounds__(256)
k_cooc_scatter(const int* __restrict__ labels,
               const int* __restrict__ lpi,
               const float* __restrict__ cooc_in,
               float* __restrict__ out)
{
    int t   = threadIdx.x;
    int bid = blockIdx.x;

    if (bid >= COOC_CTAS) {
        // ---- scatter role: one int2 label pair per thread ----
        int i = (bid - COOC_CTAS) * 256 + t;
        if (i < NROWS / 2) {
            int2 l = __ldg(reinterpret_cast<const int2*>(labels) + i);
            int p0 = atomicAdd(&g_cursor_pad[l.x * CPAD], 1);
            int p1 = atomicAdd(&g_cursor_pad[l.y * CPAD], 1);
            int r = 2 * i;
            if (p0 < SLOTS) g_rowidx[l.x * SLOTS + p0] = r + 0;
            if (p1 < SLOTS) g_rowidx[l.y * SLOTS + p1] = r + 1;
        }
        return;
    }

    // ---- cooc role ----
    __shared__ unsigned long long scol[NCLASS];
    for (int k = t; k < NCLASS; k += 256) scol[k] = 0ULL;
    __syncthreads();
    for (int k = t; k < NIMG * KPI; k += 256) {
        int img = k / KPI;
        atomicOr(&scol[__ldg(&lpi[k])], 1ULL << img);
    }
    __syncthreads();

    int i0 = bid * COOC_RPB;
    if (t < NCLASS / 4) {
        int j0 = t * 4;
        unsigned long long c0 = scol[j0 + 0];
        unsigned long long c1 = scol[j0 + 1];
        unsigned long long c2 = scol[j0 + 2];
        unsigned long long c3 = scol[j0 + 3];
        #pragma unroll
        for (int rr = 0; rr < COOC_RPB; ++rr) {
            int i = i0 + rr;
            unsigned long long bi = scol[i];
            const float4* in4 = reinterpret_cast<const float4*>(cooc_in + (size_t)i * NCLASS) + t;
            float4 v = __ldg(in4);
            v.x += (i == j0 + 0) ? 0.f : (float)__popcll(bi & c0);
            v.y += (i == j0 + 1) ? 0.f : (float)__popcll(bi & c1);
            v.z += (i == j0 + 2) ? 0.f : (float)__popcll(bi & c2);
            v.w += (i == j0 + 3) ? 0.f : (float)__popcll(bi & c3);
            reinterpret_cast<float4*>(out + OUT_COOC + (size_t)i * NCLASS)[t] = v;
        }
    }
}

// ---------------- K2: per-class normalize+sum, EMA, write protos ---------
// 1000 CTAs (one per class), 128 threads (4 warps), 8 CTAs/SM:
// 148*8 = 1184 resident slots >= 1000 CTAs -> SINGLE WAVE (R8 profile
// showed 256-thread/4-CTA config ran 1.69 waves, capping DRAM at 52%).
// Each warp owns whole rows (stride 4); lane l loads cols [8l,8l+8) as
// two float4, 4 rows in flight. Row norms via warp shfl reduce.
__global__ void __launch_bounds__(128, 8)
k_class_accum(const float* __restrict__ features,
              const float* __restrict__ prototypes,
              const int*   __restrict__ init_mask,
              const int*   __restrict__ step_ptr,
              float*       __restrict__ out)
{
    int c    = blockIdx.x;
    int tid  = threadIdx.x;
    int warp = tid >> 5;       // 0..3
    int lane = tid & 31;

    int count = min(g_cursor_pad[c * CPAD], SLOTS);
    const int* __restrict__ rows = &g_rowidx[c * SLOTS];

    float acc[8];
    #pragma unroll
    for (int j = 0; j < 8; ++j) acc[j] = 0.f;

    int r = warp;
    while (r + 12 < count) {
        int row0 = __ldg(&rows[r]);
        int row1 = __ldg(&rows[r + 4]);
        int row2 = __ldg(&rows[r + 8]);
        int row3 = __ldg(&rows[r + 12]);
        const float4* rp0 = reinterpret_cast<const float4*>(features + (size_t)row0 * FEAT);
        const float4* rp1 = reinterpret_cast<const float4*>(features + (size_t)row1 * FEAT);
        const float4* rp2 = reinterpret_cast<const float4*>(features + (size_t)row2 * FEAT);
        const float4* rp3 = reinterpret_cast<const float4*>(features + (size_t)row3 * FEAT);
        float4 a0 = __ldg(&rp0[lane * 2 + 0]);
        float4 b0 = __ldg(&rp0[lane * 2 + 1]);
        float4 a1 = __ldg(&rp1[lane * 2 + 0]);
        float4 b1 = __ldg(&rp1[lane * 2 + 1]);
        float4 a2 = __ldg(&rp2[lane * 2 + 0]);
        float4 b2 = __ldg(&rp2[lane * 2 + 1]);
        float4 a3 = __ldg(&rp3[lane * 2 + 0]);
        float4 b3 = __ldg(&rp3[lane * 2 + 1]);

        float s0 = a0.x*a0.x + a0.y*a0.y + a0.z*a0.z + a0.w*a0.w
                 + b0.x*b0.x + b0.y*b0.y + b0.z*b0.z + b0.w*b0.w;
        float s1 = a1.x*a1.x + a1.y*a1.y + a1.z*a1.z + a1.w*a1.w
                 + b1.x*b1.x + b1.y*b1.y + b1.z*b1.z + b1.w*b1.w;
        float s2 = a2.x*a2.x + a2.y*a2.y + a2.z*a2.z + a2.w*a2.w
                 + b2.x*b2.x + b2.y*b2.y + b2.z*b2.z + b2.w*b2.w;
        float s3 = a3.x*a3.x + a3.y*a3.y + a3.z*a3.z + a3.w*a3.w
                 + b3.x*b3.x + b3.y*b3.y + b3.z*b3.z + b3.w*b3.w;
        #pragma unroll
        for (int off = 16; off > 0; off >>= 1) {
            s0 += __shfl_xor_sync(0xffffffffu, s0, off);
            s1 += __shfl_xor_sync(0xffffffffu, s1, off);
            s2 += __shfl_xor_sync(0xffffffffu, s2, off);
            s3 += __shfl_xor_sync(0xffffffffu, s3, off);
        }
        float i0 = 1.0f / fmaxf(sqrtf(s0), 1e-12f);
        float i1 = 1.0f / fmaxf(sqrtf(s1), 1e-12f);
        float i2 = 1.0f / fmaxf(sqrtf(s2), 1e-12f);
        float i3 = 1.0f / fmaxf(sqrtf(s3), 1e-12f);
        acc[0] += a0.x*i0 + a1.x*i1 + a2.x*i2 + a3.x*i3;
        acc[1] += a0.y*i0 + a1.y*i1 + a2.y*i2 + a3.y*i3;
        acc[2] += a0.z*i0 + a1.z*i1 + a2.z*i2 + a3.z*i3;
        acc[3] += a0.w*i0 + a1.w*i1 + a2.w*i2 + a3.w*i3;
        acc[4] += b0.x*i0 + b1.x*i1 + b2.x*i2 + b3.x*i3;
        acc[5] += b0.y*i0 + b1.y*i1 + b2.y*i2 + b3.y*i3;
        acc[6] += b0.z*i0 + b1.z*i1 + b2.z*i2 + b3.z*i3;
        acc[7] += b0.w*i0 + b1.w*i1 + b2.w*i2 + b3.w*i3;
        r += 16;
    }
    while (r < count) {
        int row = __ldg(&rows[r]);
        const float4* rp = reinterpret_cast<const float4*>(features + (size_t)row * FEAT);
        float4 a = __ldg(&rp[lane * 2 + 0]);
        float4 b = __ldg(&rp[lane * 2 + 1]);
        float s = a.x*a.x + a.y*a.y + a.z*a.z + a.w*a.w
                + b.x*b.x + b.y*b.y + b.z*b.z + b.w*b.w;
        #pragma unroll
        for (int off = 16; off > 0; off >>= 1)
            s += __shfl_xor_sync(0xffffffffu, s, off);
        float inv = 1.0f / fmaxf(sqrtf(s), 1e-12f);
        acc[0] += a.x*inv; acc[1] += a.y*inv; acc[2] += a.z*inv; acc[3] += a.w*inv;
        acc[4] += b.x*inv; acc[5] += b.y*inv; acc[6] += b.z*inv; acc[7] += b.w*inv;
        r += 4;
    }

    // combine 4 warps' partials: warp w's lane l owns cols [8l, 8l+8)
    __shared__ float sacc[4][FEAT];
    #pragma unroll
    for (int j = 0; j < 8; ++j) sacc[warp][lane * 8 + j] = acc[j];
    __syncthreads();

    // SAFE cleanup point: barrier above guarantees every thread consumed
    // `count`; no other CTA touches g_cursor_pad[c*CPAD].
    if (tid == 0) g_cursor_pad[c * CPAD] = 0;

    int   step     = step_ptr ? __ldg(step_ptr) : 5000;
    float progress = fminf(1.0f, (float)step / 2000.0f);   // WARMUP_STEPS*10
    float m        = 0.99f + (0.999f - 0.99f) * progress;

    bool present = (count > 0);
    bool inited  = (__ldg(&init_mask[c]) > 0);
    float rcount = 1.0f / fmaxf((float)count, 1.0f);

    #pragma unroll
    for (int h = 0; h < 2; ++h) {
        int col = tid + h * 128;
        float sum = sacc[0][col] + sacc[1][col] + sacc[2][col] + sacc[3][col];
        float mean  = sum * rcount;
        float proto = __ldg(&prototypes[(size_t)c * FEAT + col]);
        float np;
        if (present && inited) np = m * proto + (1.0f - m) * mean;
        else if (present)      np = mean;
        else                   np = proto;
        out[OUT_PROTO + (size_t)c * FEAT + col] = np;
    }
    if (tid == 0)
        out[OUT_INIT + c] = (inited || present) ? 1.0f : 0.0f;
}

// ---------------- launch ------------------------------------------------
extern "C" void kernel_launch(void* const* d_in, const int* in_sizes, int n_in,
                              void* d_out, int out_size)
{
    const float* features   = (const float*)d_in[0];
    const int*   labels     = (const int*)  d_in[1];
    const int*   lpi        = (const int*)  d_in[2];
    const float* prototypes = (const float*)d_in[3];
    const int*   init_mask  = (const int*)  d_in[4];
    const float* cooc_in    = (const float*)d_in[5];
    const int*   step_ptr   = (n_in >= 7) ? (const int*)d_in[6] : nullptr;
    float*       out        = (float*)d_out;

    k_cooc_scatter<<<K1_GRID, 256>>>(labels, lpi, cooc_in, out);
    k_class_accum<<<NCLASS, 128>>>(features, prototypes, init_mask, step_ptr, out);
}